// round 10
// baseline (speedup 1.0000x reference)
#include <cuda_runtime.h>
#include <cuda_fp16.h>

// GravityDecoder, two-phase with PDL:
//   K1: pure streaming convert z(f32) -> g_zh(f16), 77MB @ LTS cap (~7us).
//   K2: per-edge gather of two 256B fp16 rows; BOTH dist2 and m_j computed
//       from the gathered rows (m_j via half2 FMA with fp16 W held in regs)
//       -> removes the 19.2MB m_j gather stream entirely.

#define MAX_N 100000
__device__ static uint4 g_zh[MAX_N * 16];   // fp16 z rows: 256 B/row

#define WARPS_PER_BLOCK 8
#define THREADS (WARPS_PER_BLOCK * 32)

// ---------------- Kernel 1: streaming fp32 -> fp16 convert ----------------
__global__ __launch_bounds__(THREADS) void precompute_kernel(
    const float* __restrict__ z, int n_chunks /* = N*128/8 */)
{
    const int tid     = (int)(blockIdx.x * (unsigned)blockDim.x + threadIdx.x);
    const int nthread = (int)(gridDim.x * (unsigned)blockDim.x);

    uint2* __restrict__ zh2 = reinterpret_cast<uint2*>(g_zh);
    const float4* __restrict__ z4 = reinterpret_cast<const float4*>(z);

    // Each chunk: 8 floats -> 8 halves (one uint2 store)
    for (int c = tid; c < n_chunks; c += nthread) {
        const float4 v0 = z4[(size_t)c * 2];
        const float4 v1 = z4[(size_t)c * 2 + 1];
        const __half2 h0 = __floats2half2_rn(v0.x, v0.y);
        const __half2 h1 = __floats2half2_rn(v0.z, v0.w);
        const __half2 h2 = __floats2half2_rn(v1.x, v1.y);
        const __half2 h3 = __floats2half2_rn(v1.z, v1.w);
        uint2 p0, p1;
        p0.x = *reinterpret_cast<const unsigned*>(&h0);
        p0.y = *reinterpret_cast<const unsigned*>(&h1);
        p1.x = *reinterpret_cast<const unsigned*>(&h2);
        p1.y = *reinterpret_cast<const unsigned*>(&h3);
        zh2[(size_t)c * 2]     = p0;
        zh2[(size_t)c * 2 + 1] = p1;
    }
    cudaTriggerProgrammaticLaunchCompletion();
}

// ---------------- Kernel 2: per-edge distance + mj + outputs ----------------
// Per half2 chunk: d2 via fp32 (convert diff), mj via hfma2 into half2 accum.
__device__ __forceinline__ void chunk_accum(uint4 A, uint4 C,
                                            const __half2* wh, // 4 half2
                                            float& d2, __half2& mjacc)
{
    const unsigned* pa = &A.x;
    const unsigned* pc = &C.x;
    #pragma unroll
    for (int k = 0; k < 4; k++) {
        const __half2 ha = *reinterpret_cast<const __half2*>(&pa[k]);
        const __half2 hc = *reinterpret_cast<const __half2*>(&pc[k]);
        const __half2 d  = __hsub2(ha, hc);
        const float2  df = __half22float2(d);
        d2 += df.x * df.x + df.y * df.y;
        mjacc = __hfma2(hc, wh[k], mjacc);
    }
}

__global__ __launch_bounds__(THREADS, 4) void gravity_decoder_kernel(
    const int* __restrict__ edge_index,
    const float* __restrict__ W,
    const float* __restrict__ b_ptr,
    float* __restrict__ out,
    int E)
{
    const int lane   = threadIdx.x & 31;
    const int sub    = lane & 3;        // sublane within 4-lane group
    const int group  = lane >> 2;       // 0..7 : which edge of the 8
    const int warp   = (int)((blockIdx.x * (unsigned)blockDim.x + threadIdx.x) >> 5);
    const int nwarps = (int)((gridDim.x * (unsigned)blockDim.x) >> 5);
    const int stride = nwarps * 8;

    float* __restrict__ out_logits = out;
    float* __restrict__ out_prob   = out + (size_t)E;
    float* __restrict__ out_mj     = out + 2 * (size_t)E;
    float* __restrict__ out_d2     = out + 3 * (size_t)E;

    // W (input, independent of K1): this lane's 32 coefficients as 16 half2,
    // grouped per chunk. Chunk c covers elements c*8 .. c*8+7.
    __half2 wh[4][4];
    {
        #pragma unroll
        for (int q = 0; q < 4; q++) {           // chunk = sub + q*4
            const int base = (sub + q * 4) * 8;
            #pragma unroll
            for (int k = 0; k < 4; k++)
                wh[q][k] = __floats2half2_rn(W[base + 2 * k], W[base + 2 * k + 1]);
        }
    }
    const float b = *b_ptr;

    int e8 = warp * 8;
    if (e8 >= E) {
        cudaGridDependencySynchronize();
        return;
    }

    // Prologue index loads (independent of K1) before the dependency sync.
    int e  = e8 + group;
    int es = (e < E) ? e : (E - 1);
    int src = __ldcs(edge_index + es);
    int dst = __ldcs(edge_index + es + (size_t)E);

    cudaGridDependencySynchronize();   // g_zh valid after this

    for (; e8 < E; e8 += stride) {
        const int  ecur  = e8 + group;
        const bool alive = (ecur < E);

        const uint4* __restrict__ zi = g_zh + (size_t)src * 16;
        const uint4* __restrict__ zj = g_zh + (size_t)dst * 16;

        // 8 gathers in flight per thread
        const uint4 A0 = zi[sub];
        const uint4 A1 = zi[sub + 4];
        const uint4 A2 = zi[sub + 8];
        const uint4 A3 = zi[sub + 12];
        const uint4 C0 = zj[sub];
        const uint4 C1 = zj[sub + 4];
        const uint4 C2 = zj[sub + 8];
        const uint4 C3 = zj[sub + 12];

        // Prefetch next iteration's indices
        const int e8n = e8 + stride;
        if (e8n < E) {
            const int en  = e8n + group;
            const int esn = (en < E) ? en : (E - 1);
            src = __ldcs(edge_index + esn);
            dst = __ldcs(edge_index + esn + (size_t)E);
        }

        float d2 = 0.0f;
        // 4 independent half2 accumulators (short rounding chains)
        __half2 m0 = __floats2half2_rn(0.f, 0.f);
        __half2 m1 = m0, m2 = m0, m3 = m0;
        chunk_accum(A0, C0, wh[0], d2, m0);
        chunk_accum(A1, C1, wh[1], d2, m1);
        chunk_accum(A2, C2, wh[2], d2, m2);
        chunk_accum(A3, C3, wh[3], d2, m3);

        const float2 f0 = __half22float2(m0);
        const float2 f1 = __half22float2(m1);
        const float2 f2 = __half22float2(m2);
        const float2 f3 = __half22float2(m3);
        float mj = (f0.x + f0.y) + (f1.x + f1.y) + (f2.x + f2.y) + (f3.x + f3.y);

        // 2-step butterfly within each 4-lane group (both scalars)
        #pragma unroll
        for (int off = 2; off > 0; off >>= 1) {
            d2 += __shfl_xor_sync(0xffffffffu, d2, off);
            mj += __shfl_xor_sync(0xffffffffu, mj, off);
        }

        mj += b;
        d2 += 1e-7f;
        const float logit = mj - __logf(d2);

        if (alive) {
            if (sub == 0)      __stcs(out_logits + ecur, logit);
            else if (sub == 1) __stcs(out_prob + ecur, __fdividef(1.0f, 1.0f + __expf(-logit)));
            else if (sub == 2) __stcs(out_mj + ecur, mj);
            else               __stcs(out_d2 + ecur, d2);
        }
    }
}

extern "C" void kernel_launch(void* const* d_in, const int* in_sizes, int n_in,
                              void* d_out, int out_size)
{
    const float* z   = (const float*)d_in[0];
    const int*   ei  = (const int*)d_in[1];
    const float* W   = (const float*)d_in[2];
    const float* b   = (const float*)d_in[3];
    float*       out = (float*)d_out;

    const int N = in_sizes[0] / 128;
    const int E = in_sizes[1] / 2;

    // K1: streaming convert, persistent grid
    const int n_chunks = N * 16;   // 8 halves per chunk
    int blocks1 = 1480;
    precompute_kernel<<<blocks1, THREADS>>>(z, n_chunks);

    // K2: 8 edges per warp, PDL overlap with K1 tail
    int blocks2 = (E + WARPS_PER_BLOCK * 8 - 1) / (WARPS_PER_BLOCK * 8);
    if (blocks2 > 4736) blocks2 = 4736;

    cudaLaunchConfig_t cfg = {};
    cfg.gridDim  = dim3((unsigned)blocks2, 1, 1);
    cfg.blockDim = dim3(THREADS, 1, 1);
    cfg.dynamicSmemBytes = 0;
    cfg.stream = 0;
    cudaLaunchAttribute attrs[1];
    attrs[0].id = cudaLaunchAttributeProgrammaticStreamSerialization;
    attrs[0].val.programmaticStreamSerializationAllowed = 1;
    cfg.attrs = attrs;
    cfg.numAttrs = 1;
    cudaLaunchKernelEx(&cfg, gravity_decoder_kernel, ei, W, b, out, E);
}